// round 7
// baseline (speedup 1.0000x reference)
#include <cuda_runtime.h>
#include <math.h>
#include <stdint.h>

#define N_NODES 100000
#define N_EDGES 1600000

// -------- scratch (static device allocation; no cudaMalloc anywhere) --------
__device__ float g_xr[(size_t)N_NODES * 128];   // x rounded to tf32
__device__ float g_t[(size_t)N_NODES * 128];    // X @ Wn  (neighbor projection, pre-aggregation)
__device__ float g_ts[(size_t)N_NODES * 128];   // X @ Ws  (self projection, raw, no bias)
__device__ float g_h1[(size_t)N_NODES * 256];   // layer-1 output (tf32-rounded)
__device__ float g_h2[(size_t)N_NODES * 256];   // layer-2 output (tf32-rounded, feeds head MMA)
__device__ float g_cnt[N_NODES];                // in-degree (float)
__device__ int   g_deg[N_NODES];
__device__ int   g_cursor[N_NODES];
__device__ int   g_rowptr[N_NODES + 1];
__device__ int   g_adj[N_EDGES];
__device__ float g_wswz[(128 + 128 + 256 + 256) * 128];  // pre-swizzled tf32 weights
__device__ float g_wfcr[256 * 40];                       // wfc rounded to tf32

#define W1N_OFF 0
#define W1S_OFF (128 * 128)
#define W2N_OFF (2 * 128 * 128)
#define W2S_OFF (2 * 128 * 128 + 256 * 128)

// ---------------------------------------------------------------------------
__device__ __forceinline__ float to_tf32(float x) {
    asm("cvt.rna.tf32.f32 %0, %1;" : "=f"(x) : "f"(x));
    return x;
}

__device__ __forceinline__ void swz_one(const float* __restrict__ w, int off, int i) {
    int k = i >> 7, n = i & 127;
    g_wswz[off + k * 128 + (n & 7) * 16 + (n >> 3)] = to_tf32(w[i]);
}

// zero deg/cursor (must precede count_kernel)
__global__ void zero_dc_kernel() {
    int i = blockIdx.x * blockDim.x + threadIdx.x;
    if (i < N_NODES) { g_deg[i] = 0; g_cursor[i] = 0; }
}

// prepass: round x + wfc to tf32, swizzle+round 4 weight mats
__global__ void prep_kernel(const float* __restrict__ x,
                            const float* __restrict__ w1n, const float* __restrict__ w1s,
                            const float* __restrict__ w2n, const float* __restrict__ w2s,
                            const float* __restrict__ wfc) {
    int idx = blockIdx.x * blockDim.x + threadIdx.x;
    int stride = gridDim.x * blockDim.x;
    for (int i = idx; i < N_NODES * 32; i += stride) {
        float4 v = ((const float4*)x)[i];
        v.x = to_tf32(v.x); v.y = to_tf32(v.y); v.z = to_tf32(v.z); v.w = to_tf32(v.w);
        ((float4*)g_xr)[i] = v;
    }
    for (int i = idx; i < 128 * 128; i += stride) swz_one(w1n, W1N_OFF, i);
    for (int i = idx; i < 128 * 128; i += stride) swz_one(w1s, W1S_OFF, i);
    for (int i = idx; i < 256 * 128; i += stride) swz_one(w2n, W2N_OFF, i);
    for (int i = idx; i < 256 * 128; i += stride) swz_one(w2s, W2S_OFF, i);
    for (int i = idx; i < 256 * 40; i += stride) g_wfcr[i] = to_tf32(wfc[i]);
}

// ---------------------------------------------------------------------------
// CSR build
__global__ void count_kernel(const int* __restrict__ dst) {
    int e4 = blockIdx.x * blockDim.x + threadIdx.x;
    int base = e4 * 4;
    if (base + 4 <= N_EDGES) {
        int4 d = *(const int4*)&dst[base];
        atomicAdd(&g_deg[d.x], 1);
        atomicAdd(&g_deg[d.y], 1);
        atomicAdd(&g_deg[d.z], 1);
        atomicAdd(&g_deg[d.w], 1);
    } else {
        for (int e = base; e < N_EDGES; ++e) atomicAdd(&g_deg[dst[e]], 1);
    }
}

__global__ __launch_bounds__(1024)
void scan_kernel() {
    __shared__ int wsum[32];
    __shared__ int carry_s;
    int tid = threadIdx.x, lane = tid & 31, wid = tid >> 5;
    if (tid == 0) carry_s = 0;
    __syncthreads();
    for (int base = 0; base < N_NODES; base += 1024) {
        int carry = carry_s;
        int i = base + tid;
        int v = (i < N_NODES) ? g_deg[i] : 0;
        int x = v;
#pragma unroll
        for (int o = 1; o < 32; o <<= 1) {
            int y = __shfl_up_sync(0xffffffffu, x, o);
            if (lane >= o) x += y;
        }
        if (lane == 31) wsum[wid] = x;
        __syncthreads();
        if (wid == 0) {
            int s = wsum[lane];
#pragma unroll
            for (int o = 1; o < 32; o <<= 1) {
                int y = __shfl_up_sync(0xffffffffu, s, o);
                if (lane >= o) s += y;
            }
            wsum[lane] = s;
        }
        __syncthreads();
        int incl = x + (wid ? wsum[wid - 1] : 0) + carry;
        if (i < N_NODES) { g_rowptr[i] = incl - v; g_cnt[i] = (float)v; }
        __syncthreads();
        if (tid == 1023) carry_s = incl;
        __syncthreads();
    }
    if (threadIdx.x == 0) g_rowptr[N_NODES] = carry_s;
}

__global__ void fill_kernel(const int* __restrict__ src, const int* __restrict__ dst) {
    int e = blockIdx.x * blockDim.x + threadIdx.x;
    if (e < N_EDGES) {
        int d = dst[e];
        int pos = atomicAdd(&g_cursor[d], 1);
        g_adj[g_rowptr[d] + pos] = src[e];
    }
}

// ---------------------------------------------------------------------------
// gather + full SAGE epilogue (one warp per node), unroll-4 on neighbors.
template <int LAYER>
__global__ __launch_bounds__(256)
void gather_epi_kernel(const float* __restrict__ bs, const float* __restrict__ bn) {
    int gw = (blockIdx.x * blockDim.x + threadIdx.x) >> 5;
    int lane = threadIdx.x & 31;
    if (gw >= N_NODES) return;
    int beg = g_rowptr[gw];
    int end = g_rowptr[gw + 1];
    const int c4 = lane * 4;

    float4 accA = make_float4(0.f, 0.f, 0.f, 0.f);
    float4 accB = make_float4(0.f, 0.f, 0.f, 0.f);
    for (int i = beg; i < end; i += 32) {
        int id = (i + lane < end) ? g_adj[i + lane] : 0;
        int m = min(32, end - i);
        int j = 0;
        for (; j + 4 <= m; j += 4) {
            int s0 = __shfl_sync(0xffffffffu, id, j);
            int s1 = __shfl_sync(0xffffffffu, id, j + 1);
            int s2 = __shfl_sync(0xffffffffu, id, j + 2);
            int s3 = __shfl_sync(0xffffffffu, id, j + 3);
            float4 v0 = __ldg((const float4*)&g_t[(size_t)s0 * 128 + c4]);
            float4 v1 = __ldg((const float4*)&g_t[(size_t)s1 * 128 + c4]);
            float4 v2 = __ldg((const float4*)&g_t[(size_t)s2 * 128 + c4]);
            float4 v3 = __ldg((const float4*)&g_t[(size_t)s3 * 128 + c4]);
            accA.x += v0.x + v1.x; accA.y += v0.y + v1.y;
            accA.z += v0.z + v1.z; accA.w += v0.w + v1.w;
            accB.x += v2.x + v3.x; accB.y += v2.y + v3.y;
            accB.z += v2.z + v3.z; accB.w += v2.w + v3.w;
        }
        for (; j < m; ++j) {
            int s0 = __shfl_sync(0xffffffffu, id, j);
            float4 v0 = __ldg((const float4*)&g_t[(size_t)s0 * 128 + c4]);
            accA.x += v0.x; accA.y += v0.y; accA.z += v0.z; accA.w += v0.w;
        }
    }
    float4 acc = make_float4(accA.x + accB.x, accA.y + accB.y,
                             accA.z + accB.z, accA.w + accB.w);

    float inv = 1.f / fmaxf(g_cnt[gw], 1.f);
    float4 ts  = *(const float4*)&g_ts[(size_t)gw * 128 + c4];
    float4 bsv = *(const float4*)&bs[c4];
    float4 bnv = *(const float4*)&bn[c4];

    float s0 = fmaxf(ts.x + bsv.x, 0.f), s1 = fmaxf(ts.y + bsv.y, 0.f);
    float s2 = fmaxf(ts.z + bsv.z, 0.f), s3 = fmaxf(ts.w + bsv.w, 0.f);
    float a0 = fmaxf(acc.x * inv + bnv.x, 0.f), a1 = fmaxf(acc.y * inv + bnv.y, 0.f);
    float a2 = fmaxf(acc.z * inv + bnv.z, 0.f), a3 = fmaxf(acc.w * inv + bnv.w, 0.f);

    float ss = s0 * s0 + s1 * s1 + s2 * s2 + s3 * s3
             + a0 * a0 + a1 * a1 + a2 * a2 + a3 * a3;
#pragma unroll
    for (int o = 16; o > 0; o >>= 1) ss += __shfl_xor_sync(0xffffffffu, ss, o);
    float sc = 1.f / fmaxf(sqrtf(ss), 1e-12f);

    s0 = to_tf32(s0 * sc); s1 = to_tf32(s1 * sc); s2 = to_tf32(s2 * sc); s3 = to_tf32(s3 * sc);
    a0 = to_tf32(a0 * sc); a1 = to_tf32(a1 * sc); a2 = to_tf32(a2 * sc); a3 = to_tf32(a3 * sc);
    float* H = (LAYER == 1) ? g_h1 : g_h2;
    *(float4*)&H[(size_t)gw * 256 + c4]       = make_float4(s0, s1, s2, s3);
    *(float4*)&H[(size_t)gw * 256 + 128 + c4] = make_float4(a0, a1, a2, a3);
}

// ---------------------------------------------------------------------------
__device__ __forceinline__ void mma_tf32(float c[4],
                                         uint32_t a0, uint32_t a1, uint32_t a2, uint32_t a3,
                                         uint32_t b0, uint32_t b1) {
    asm volatile(
        "mma.sync.aligned.m16n8k8.row.col.f32.tf32.tf32.f32 "
        "{%0,%1,%2,%3}, {%4,%5,%6,%7}, {%8,%9}, {%0,%1,%2,%3};"
        : "+f"(c[0]), "+f"(c[1]), "+f"(c[2]), "+f"(c[3])
        : "r"(a0), "r"(a1), "r"(a2), "r"(a3), "r"(b0), "r"(b1));
}

__device__ __forceinline__ void cp_cg(uint32_t d, const void* s) {
    asm volatile("cp.async.cg.shared.global [%0], [%1], 16;" :: "r"(d), "l"(s));
}
__device__ __forceinline__ void cp_commit() { asm volatile("cp.async.commit_group;"); }
template <int NW>
__device__ __forceinline__ void cp_wait() { asm volatile("cp.async.wait_group %0;" :: "n"(NW)); }

// GEMM (tf32 tensor cores, cp.async 3-stage pipeline): both projections per layer.
//   blockIdx.y==0: X @ W[woffN] -> g_t ;  blockIdx.y==1: X @ W[woffS] -> g_ts
// Block 128x128, 8 warps; warp = 16 rows x 128 cols. 2 blocks/SM.
template <int K>
__global__ __launch_bounds__(256, 2)
void sage_gemm_tc(int woffN, int woffS) {
    constexpr int XS = 36;
    constexpr int WS = 132;
    constexpr int XB = 128 * XS;
    constexpr int WB = 32 * WS;
    constexpr int NKB = K / 32;
    constexpr int ST = 3;          // pipeline stages

    extern __shared__ float smem[];
    float* Xs = smem;              // ST buffers
    float* Ws = smem + ST * XB;    // ST buffers

    const int tid = threadIdx.x;
    const int lane = tid & 31;
    const int w = tid >> 5;
    const int g = lane >> 2;
    const int t = lane & 3;
    const int rowBase = blockIdx.x * 128;
    const float* X = (K == 256) ? (const float*)g_h1 : (const float*)g_xr;
    const float* Wg = g_wswz + (blockIdx.y ? woffS : woffN);
    float* dstbuf = blockIdx.y ? g_ts : g_t;

    const uint32_t xs_base = (uint32_t)__cvta_generic_to_shared(Xs);
    const uint32_t ws_base = (uint32_t)__cvta_generic_to_shared(Ws);

    float c[16][4];
#pragma unroll
    for (int i = 0; i < 16; ++i) { c[i][0] = c[i][1] = c[i][2] = c[i][3] = 0.f; }

    auto stage = [&](int buf, int kb) {
#pragma unroll
        for (int it = 0; it < 4; ++it) {
            int idx = tid + it * 256;
            int r = idx >> 3, cc = idx & 7;
            int grow = min(rowBase + r, N_NODES - 1);
            uint32_t d = xs_base + (uint32_t)buf * XB * 4 + r * 144 + cc * 16;
            cp_cg(d, &X[(size_t)grow * K + kb * 32 + cc * 4]);
        }
#pragma unroll
        for (int it = 0; it < 4; ++it) {
            int idx = tid + it * 256;
            int r = idx >> 5, cc = idx & 31;
            uint32_t d = ws_base + (uint32_t)buf * WB * 4 + r * 528 + cc * 16;
            cp_cg(d, &Wg[(size_t)(kb * 32 + r) * 128 + cc * 4]);
        }
    };

    // prologue: two tiles in flight
    stage(0, 0); cp_commit();
    if (NKB > 1) { stage(1, 1); cp_commit(); }

#pragma unroll
    for (int kb = 0; kb < NKB; ++kb) {
        if (kb + 2 < NKB) { stage((kb + 2) % ST, kb + 2); cp_commit(); }
        if (kb + 2 < NKB)      cp_wait<2>();
        else if (kb + 1 < NKB) cp_wait<1>();
        else                   cp_wait<0>();
        __syncthreads();

        const uint32_t* Xu = (const uint32_t*)(Xs + (kb % ST) * XB);
        const uint32_t* Wu = (const uint32_t*)(Ws + (kb % ST) * WB);
#pragma unroll
        for (int ks = 0; ks < 4; ++ks) {
            const int kl = ks * 8;
            const int ar = w * 16 + g;
            uint32_t a0 = Xu[ar * XS + kl + t];
            uint32_t a1 = Xu[(ar + 8) * XS + kl + t];
            uint32_t a2 = Xu[ar * XS + kl + t + 4];
            uint32_t a3 = Xu[(ar + 8) * XS + kl + t + 4];
            uint4 blo[4], bhi[4];
#pragma unroll
            for (int q = 0; q < 4; ++q) {
                blo[q] = *(const uint4*)&Wu[(kl + t) * WS + g * 16 + q * 4];
                bhi[q] = *(const uint4*)&Wu[(kl + t + 4) * WS + g * 16 + q * 4];
            }
#pragma unroll
            for (int nt = 0; nt < 16; ++nt) {
                uint32_t b0 = ((const uint32_t*)&blo[nt >> 2])[nt & 3];
                uint32_t b1 = ((const uint32_t*)&bhi[nt >> 2])[nt & 3];
                mma_tf32(c[nt], a0, a1, a2, a3, b0, b1);
            }
        }
        __syncthreads();
    }

    const int r1 = rowBase + w * 16 + g;
    const int r2 = r1 + 8;
    const bool v1 = r1 < N_NODES;
    const bool v2 = r2 < N_NODES;
#pragma unroll
    for (int nt = 0; nt < 16; ++nt) {
        int col = nt * 8 + 2 * t;
        if (v1) *(float2*)&dstbuf[(size_t)r1 * 128 + col] = make_float2(c[nt][0], c[nt][1]);
        if (v2) *(float2*)&dstbuf[(size_t)r2 * 128 + col] = make_float2(c[nt][2], c[nt][3]);
    }
}

// ---------------------------------------------------------------------------
// head (tf32 MMA): out[N,40] = h2[N,256] @ wfcr[256,40] + bfc
__global__ __launch_bounds__(256)
void head_tc(const float* __restrict__ bfc, float* __restrict__ out) {
    constexpr int XS = 36;
    constexpr int XB = 128 * XS;
    constexpr int WSTR = 44;

    extern __shared__ float smem[];
    float* Xs = smem;                  // 2 * XB floats
    float* Wsm = smem + 2 * XB;        // 256 * 44 floats

    const int tid = threadIdx.x;
    const int lane = tid & 31;
    const int w = tid >> 5;
    const int g = lane >> 2;
    const int t = lane & 3;
    const int rowBase = blockIdx.x * 128;

    const uint32_t xs_base = (uint32_t)__cvta_generic_to_shared(Xs);

    auto stageX = [&](int buf, int kb) {
#pragma unroll
        for (int it = 0; it < 4; ++it) {
            int idx = tid + it * 256;
            int r = idx >> 3, cc = idx & 7;
            int grow = min(rowBase + r, N_NODES - 1);
            uint32_t d = xs_base + (uint32_t)buf * XB * 4 + r * 144 + cc * 16;
            cp_cg(d, &g_h2[(size_t)grow * 256 + kb * 32 + cc * 4]);
        }
    };

    stageX(0, 0);
    cp_commit();

    for (int i = tid; i < 256 * 40; i += 256) {
        int k = i / 40, n = i % 40;
        Wsm[k * WSTR + n] = g_wfcr[i];
    }

    float c[5][4];
#pragma unroll
    for (int i = 0; i < 5; ++i) { c[i][0] = c[i][1] = c[i][2] = c[i][3] = 0.f; }

#pragma unroll
    for (int kb = 0; kb < 8; ++kb) {
        if (kb + 1 < 8) {
            stageX((kb + 1) & 1, kb + 1);
            cp_commit();
            cp_wait<1>();
        } else {
            cp_wait<0>();
        }
        __syncthreads();

        const uint32_t* Xu = (const uint32_t*)(Xs + (kb & 1) * XB);
#pragma unroll
        for (int ks = 0; ks < 4; ++ks) {
            const int kl = ks * 8;
            const int ar = w * 16 + g;
            uint32_t a0 = Xu[ar * XS + kl + t];
            uint32_t a1 = Xu[(ar + 8) * XS + kl + t];
            uint32_t a2 = Xu[ar * XS + kl + t + 4];
            uint32_t a3 = Xu[(ar + 8) * XS + kl + t + 4];
            const int krow = kb * 32 + kl;
#pragma unroll
            for (int nt = 0; nt < 5; ++nt) {
                uint32_t b0 = __float_as_uint(Wsm[(krow + t) * WSTR + nt * 8 + g]);
                uint32_t b1 = __float_as_uint(Wsm[(krow + t + 4) * WSTR + nt * 8 + g]);
                mma_tf32(c[nt], a0, a1, a2, a3, b0, b1);
            }
        }
        __syncthreads();
    }

    const int r1 = rowBase + w * 16 + g;
    const int r2 = r1 + 8;
#pragma unroll
    for (int nt = 0; nt < 5; ++nt) {
        int col = nt * 8 + 2 * t;
        float2 b = *(const float2*)&bfc[col];
        if (r1 < N_NODES) *(float2*)&out[(size_t)r1 * 40 + col] = make_float2(c[nt][0] + b.x, c[nt][1] + b.y);
        if (r2 < N_NODES) *(float2*)&out[(size_t)r2 * 40 + col] = make_float2(c[nt][2] + b.x, c[nt][3] + b.y);
    }
}

// ---------------------------------------------------------------------------
extern "C" void kernel_launch(void* const* d_in, const int* in_sizes, int n_in,
                              void* d_out, int out_size) {
    const float* x   = (const float*)d_in[0];
    const int*   src = (const int*)d_in[1];
    const int*   dst = (const int*)d_in[2];
    const float* w1s = (const float*)d_in[3];
    const float* b1s = (const float*)d_in[4];
    const float* w1n = (const float*)d_in[5];
    const float* b1n = (const float*)d_in[6];
    const float* w2s = (const float*)d_in[7];
    const float* b2s = (const float*)d_in[8];
    const float* w2n = (const float*)d_in[9];
    const float* b2n = (const float*)d_in[10];
    const float* wfc = (const float*)d_in[11];
    const float* bfc = (const float*)d_in[12];
    float* out = (float*)d_out;

    const int SMEM_GEMM = 3 * (128 * 36 + 32 * 132) * 4;         // 105984
    const int SMEM_HEAD = (2 * 128 * 36 + 256 * 44) * 4;         // 81920
    static int attr_done = 0;
    if (!attr_done) {
        cudaFuncSetAttribute(sage_gemm_tc<128>, cudaFuncAttributeMaxDynamicSharedMemorySize, SMEM_GEMM);
        cudaFuncSetAttribute(sage_gemm_tc<256>, cudaFuncAttributeMaxDynamicSharedMemorySize, SMEM_GEMM);
        cudaFuncSetAttribute(head_tc, cudaFuncAttributeMaxDynamicSharedMemorySize, SMEM_HEAD);
        attr_done = 1;
    }

    const dim3 gemm_grid((N_NODES + 127) / 128, 2);
    const int gath_blocks = (N_NODES + 7) / 8;
    const int edge_blocks = (N_EDGES + 255) / 256;
    const int head_blocks = (N_NODES + 127) / 128;

    // order chosen so the ncu capture slot (our launch #4) hits sage_gemm_tc<128>
    zero_dc_kernel<<<(N_NODES + 255) / 256, 256>>>();                      // 1
    count_kernel<<<(N_EDGES / 4 + 255) / 256, 256>>>(dst);                 // 2
    prep_kernel<<<2048, 256>>>(x, w1n, w1s, w2n, w2s, wfc);                // 3
    sage_gemm_tc<128><<<gemm_grid, 256, SMEM_GEMM>>>(W1N_OFF, W1S_OFF);    // 4  <- profiled
    scan_kernel<<<1, 1024>>>();                                            // 5
    fill_kernel<<<edge_blocks, 256>>>(src, dst);                           // 6
    gather_epi_kernel<1><<<gath_blocks, 256>>>(b1s, b1n);                  // 7
    sage_gemm_tc<256><<<gemm_grid, 256, SMEM_GEMM>>>(W2N_OFF, W2S_OFF);    // 8
    gather_epi_kernel<2><<<gath_blocks, 256>>>(b2s, b2n);                  // 9
    head_tc<<<head_blocks, 256, SMEM_HEAD>>>(bfc, out);                    // 10
}

// round 8
// speedup vs baseline: 1.0651x; 1.0651x over previous
#include <cuda_runtime.h>
#include <cuda_fp16.h>
#include <math.h>
#include <stdint.h>

#define N_NODES 100000
#define N_EDGES 1600000

// -------- scratch (static device allocation; no cudaMalloc anywhere) --------
__device__ float  g_xr[(size_t)N_NODES * 128];   // x rounded to tf32
__device__ __half g_t[(size_t)N_NODES * 128];    // X @ Wn  (neighbor projection, fp16)
__device__ __half g_ts[(size_t)N_NODES * 128];   // X @ Ws  (self projection, fp16)
__device__ float  g_h1[(size_t)N_NODES * 256];   // layer-1 output (tf32-rounded)
__device__ float  g_h2[(size_t)N_NODES * 256];   // layer-2 output (tf32-rounded)
__device__ float  g_cnt[N_NODES];                // in-degree (float)
__device__ int    g_deg[N_NODES];
__device__ int    g_cursor[N_NODES];
__device__ int    g_rowptr[N_NODES + 1];
__device__ int    g_adj[N_EDGES];
__device__ float  g_wswz[(128 + 128 + 256 + 256) * 128];  // pre-swizzled tf32 weights
__device__ float  g_wfcr[256 * 40];                       // wfc rounded to tf32

#define W1N_OFF 0
#define W1S_OFF (128 * 128)
#define W2N_OFF (2 * 128 * 128)
#define W2S_OFF (2 * 128 * 128 + 256 * 128)

// ---------------------------------------------------------------------------
__device__ __forceinline__ float to_tf32(float x) {
    asm("cvt.rna.tf32.f32 %0, %1;" : "=f"(x) : "f"(x));
    return x;
}

__device__ __forceinline__ void swz_one(const float* __restrict__ w, int off, int i) {
    int k = i >> 7, n = i & 127;
    g_wswz[off + k * 128 + (n & 7) * 16 + (n >> 3)] = to_tf32(w[i]);
}

// zero deg/cursor (must precede count_kernel)
__global__ void zero_dc_kernel() {
    int i = blockIdx.x * blockDim.x + threadIdx.x;
    if (i < N_NODES) { g_deg[i] = 0; g_cursor[i] = 0; }
}

// prepass: round x + wfc to tf32, swizzle+round 4 weight mats
__global__ void prep_kernel(const float* __restrict__ x,
                            const float* __restrict__ w1n, const float* __restrict__ w1s,
                            const float* __restrict__ w2n, const float* __restrict__ w2s,
                            const float* __restrict__ wfc) {
    int idx = blockIdx.x * blockDim.x + threadIdx.x;
    int stride = gridDim.x * blockDim.x;
    for (int i = idx; i < N_NODES * 32; i += stride) {
        float4 v = ((const float4*)x)[i];
        v.x = to_tf32(v.x); v.y = to_tf32(v.y); v.z = to_tf32(v.z); v.w = to_tf32(v.w);
        ((float4*)g_xr)[i] = v;
    }
    for (int i = idx; i < 128 * 128; i += stride) swz_one(w1n, W1N_OFF, i);
    for (int i = idx; i < 128 * 128; i += stride) swz_one(w1s, W1S_OFF, i);
    for (int i = idx; i < 256 * 128; i += stride) swz_one(w2n, W2N_OFF, i);
    for (int i = idx; i < 256 * 128; i += stride) swz_one(w2s, W2S_OFF, i);
    for (int i = idx; i < 256 * 40; i += stride) g_wfcr[i] = to_tf32(wfc[i]);
}

// ---------------------------------------------------------------------------
// CSR build
__global__ void count_kernel(const int* __restrict__ dst) {
    int e4 = blockIdx.x * blockDim.x + threadIdx.x;
    int base = e4 * 4;
    if (base + 4 <= N_EDGES) {
        int4 d = *(const int4*)&dst[base];
        atomicAdd(&g_deg[d.x], 1);
        atomicAdd(&g_deg[d.y], 1);
        atomicAdd(&g_deg[d.z], 1);
        atomicAdd(&g_deg[d.w], 1);
    } else {
        for (int e = base; e < N_EDGES; ++e) atomicAdd(&g_deg[dst[e]], 1);
    }
}

__global__ __launch_bounds__(1024)
void scan_kernel() {
    __shared__ int wsum[32];
    __shared__ int carry_s;
    int tid = threadIdx.x, lane = tid & 31, wid = tid >> 5;
    if (tid == 0) carry_s = 0;
    __syncthreads();
    for (int base = 0; base < N_NODES; base += 1024) {
        int carry = carry_s;
        int i = base + tid;
        int v = (i < N_NODES) ? g_deg[i] : 0;
        int x = v;
#pragma unroll
        for (int o = 1; o < 32; o <<= 1) {
            int y = __shfl_up_sync(0xffffffffu, x, o);
            if (lane >= o) x += y;
        }
        if (lane == 31) wsum[wid] = x;
        __syncthreads();
        if (wid == 0) {
            int s = wsum[lane];
#pragma unroll
            for (int o = 1; o < 32; o <<= 1) {
                int y = __shfl_up_sync(0xffffffffu, s, o);
                if (lane >= o) s += y;
            }
            wsum[lane] = s;
        }
        __syncthreads();
        int incl = x + (wid ? wsum[wid - 1] : 0) + carry;
        if (i < N_NODES) { g_rowptr[i] = incl - v; g_cnt[i] = (float)v; }
        __syncthreads();
        if (tid == 1023) carry_s = incl;
        __syncthreads();
    }
    if (threadIdx.x == 0) g_rowptr[N_NODES] = carry_s;
}

__global__ void fill_kernel(const int* __restrict__ src, const int* __restrict__ dst) {
    int e = blockIdx.x * blockDim.x + threadIdx.x;
    if (e < N_EDGES) {
        int d = dst[e];
        int pos = atomicAdd(&g_cursor[d], 1);
        g_adj[g_rowptr[d] + pos] = src[e];
    }
}

// ---------------------------------------------------------------------------
// fp16 row helpers: lane covers cols c4..c4+3 => one 8-byte load (2x half2)
__device__ __forceinline__ float4 ld_t4(const __half* base, size_t off) {
    uint2 u = __ldg((const uint2*)(base + off));
    __half2 h0 = *reinterpret_cast<__half2*>(&u.x);
    __half2 h1 = *reinterpret_cast<__half2*>(&u.y);
    float2 f0 = __half22float2(h0);
    float2 f1 = __half22float2(h1);
    return make_float4(f0.x, f0.y, f1.x, f1.y);
}

// gather + full SAGE epilogue (one warp per node), unroll-4 on neighbors.
template <int LAYER>
__global__ __launch_bounds__(256)
void gather_epi_kernel(const float* __restrict__ bs, const float* __restrict__ bn) {
    int gw = (blockIdx.x * blockDim.x + threadIdx.x) >> 5;
    int lane = threadIdx.x & 31;
    if (gw >= N_NODES) return;
    int beg = g_rowptr[gw];
    int end = g_rowptr[gw + 1];
    const int c4 = lane * 4;

    float4 accA = make_float4(0.f, 0.f, 0.f, 0.f);
    float4 accB = make_float4(0.f, 0.f, 0.f, 0.f);
    for (int i = beg; i < end; i += 32) {
        int id = (i + lane < end) ? g_adj[i + lane] : 0;
        int m = min(32, end - i);
        int j = 0;
        for (; j + 4 <= m; j += 4) {
            int s0 = __shfl_sync(0xffffffffu, id, j);
            int s1 = __shfl_sync(0xffffffffu, id, j + 1);
            int s2 = __shfl_sync(0xffffffffu, id, j + 2);
            int s3 = __shfl_sync(0xffffffffu, id, j + 3);
            float4 v0 = ld_t4(g_t, (size_t)s0 * 128 + c4);
            float4 v1 = ld_t4(g_t, (size_t)s1 * 128 + c4);
            float4 v2 = ld_t4(g_t, (size_t)s2 * 128 + c4);
            float4 v3 = ld_t4(g_t, (size_t)s3 * 128 + c4);
            accA.x += v0.x + v1.x; accA.y += v0.y + v1.y;
            accA.z += v0.z + v1.z; accA.w += v0.w + v1.w;
            accB.x += v2.x + v3.x; accB.y += v2.y + v3.y;
            accB.z += v2.z + v3.z; accB.w += v2.w + v3.w;
        }
        for (; j < m; ++j) {
            int s0 = __shfl_sync(0xffffffffu, id, j);
            float4 v0 = ld_t4(g_t, (size_t)s0 * 128 + c4);
            accA.x += v0.x; accA.y += v0.y; accA.z += v0.z; accA.w += v0.w;
        }
    }
    float4 acc = make_float4(accA.x + accB.x, accA.y + accB.y,
                             accA.z + accB.z, accA.w + accB.w);

    float inv = 1.f / fmaxf(g_cnt[gw], 1.f);
    float4 ts  = ld_t4(g_ts, (size_t)gw * 128 + c4);
    float4 bsv = *(const float4*)&bs[c4];
    float4 bnv = *(const float4*)&bn[c4];

    float s0 = fmaxf(ts.x + bsv.x, 0.f), s1 = fmaxf(ts.y + bsv.y, 0.f);
    float s2 = fmaxf(ts.z + bsv.z, 0.f), s3 = fmaxf(ts.w + bsv.w, 0.f);
    float a0 = fmaxf(acc.x * inv + bnv.x, 0.f), a1 = fmaxf(acc.y * inv + bnv.y, 0.f);
    float a2 = fmaxf(acc.z * inv + bnv.z, 0.f), a3 = fmaxf(acc.w * inv + bnv.w, 0.f);

    float ss = s0 * s0 + s1 * s1 + s2 * s2 + s3 * s3
             + a0 * a0 + a1 * a1 + a2 * a2 + a3 * a3;
#pragma unroll
    for (int o = 16; o > 0; o >>= 1) ss += __shfl_xor_sync(0xffffffffu, ss, o);
    float sc = 1.f / fmaxf(sqrtf(ss), 1e-12f);

    s0 = to_tf32(s0 * sc); s1 = to_tf32(s1 * sc); s2 = to_tf32(s2 * sc); s3 = to_tf32(s3 * sc);
    a0 = to_tf32(a0 * sc); a1 = to_tf32(a1 * sc); a2 = to_tf32(a2 * sc); a3 = to_tf32(a3 * sc);
    float* H = (LAYER == 1) ? g_h1 : g_h2;
    *(float4*)&H[(size_t)gw * 256 + c4]       = make_float4(s0, s1, s2, s3);
    *(float4*)&H[(size_t)gw * 256 + 128 + c4] = make_float4(a0, a1, a2, a3);
}

// ---------------------------------------------------------------------------
__device__ __forceinline__ void mma_tf32(float c[4],
                                         uint32_t a0, uint32_t a1, uint32_t a2, uint32_t a3,
                                         uint32_t b0, uint32_t b1) {
    asm volatile(
        "mma.sync.aligned.m16n8k8.row.col.f32.tf32.tf32.f32 "
        "{%0,%1,%2,%3}, {%4,%5,%6,%7}, {%8,%9}, {%0,%1,%2,%3};"
        : "+f"(c[0]), "+f"(c[1]), "+f"(c[2]), "+f"(c[3])
        : "r"(a0), "r"(a1), "r"(a2), "r"(a3), "r"(b0), "r"(b1));
}

__device__ __forceinline__ void cp_cg(uint32_t d, const void* s) {
    asm volatile("cp.async.cg.shared.global [%0], [%1], 16;" :: "r"(d), "l"(s));
}
__device__ __forceinline__ void cp_commit() { asm volatile("cp.async.commit_group;"); }
template <int NW>
__device__ __forceinline__ void cp_wait() { asm volatile("cp.async.wait_group %0;" :: "n"(NW)); }

// GEMM (tf32 tensor cores, cp.async double-buffered): both projections per layer.
//   blockIdx.y==0: X @ W[woffN] -> g_t ;  blockIdx.y==1: X @ W[woffS] -> g_ts
// Outputs stored fp16. Block 128x128, 8 warps; warp = 16 rows x 128 cols.
template <int K>
__global__ __launch_bounds__(256)
void sage_gemm_tc(int woffN, int woffS) {
    constexpr int XS = 36;
    constexpr int WS = 132;
    constexpr int XB = 128 * XS;
    constexpr int WB = 32 * WS;
    constexpr int NKB = K / 32;

    extern __shared__ float smem[];
    float* Xs = smem;
    float* Ws = smem + 2 * XB;

    const int tid = threadIdx.x;
    const int lane = tid & 31;
    const int w = tid >> 5;
    const int g = lane >> 2;
    const int t = lane & 3;
    const int rowBase = blockIdx.x * 128;
    const float* X = (K == 256) ? (const float*)g_h1 : (const float*)g_xr;
    const float* Wg = g_wswz + (blockIdx.y ? woffS : woffN);
    __half* dstbuf = blockIdx.y ? g_ts : g_t;

    const uint32_t xs_base = (uint32_t)__cvta_generic_to_shared(Xs);
    const uint32_t ws_base = (uint32_t)__cvta_generic_to_shared(Ws);

    float c[16][4];
#pragma unroll
    for (int i = 0; i < 16; ++i) { c[i][0] = c[i][1] = c[i][2] = c[i][3] = 0.f; }

    auto stage = [&](int buf, int kb) {
#pragma unroll
        for (int it = 0; it < 4; ++it) {
            int idx = tid + it * 256;
            int r = idx >> 3, cc = idx & 7;
            int grow = min(rowBase + r, N_NODES - 1);
            uint32_t d = xs_base + (uint32_t)buf * XB * 4 + r * 144 + cc * 16;
            cp_cg(d, &X[(size_t)grow * K + kb * 32 + cc * 4]);
        }
#pragma unroll
        for (int it = 0; it < 4; ++it) {
            int idx = tid + it * 256;
            int r = idx >> 5, cc = idx & 31;
            uint32_t d = ws_base + (uint32_t)buf * WB * 4 + r * 528 + cc * 16;
            cp_cg(d, &Wg[(size_t)(kb * 32 + r) * 128 + cc * 4]);
        }
    };

    stage(0, 0);
    cp_commit();

#pragma unroll
    for (int kb = 0; kb < NKB; ++kb) {
        if (kb + 1 < NKB) {
            stage((kb + 1) & 1, kb + 1);
            cp_commit();
            cp_wait<1>();
        } else {
            cp_wait<0>();
        }
        __syncthreads();

        const uint32_t* Xu = (const uint32_t*)(Xs + (kb & 1) * XB);
        const uint32_t* Wu = (const uint32_t*)(Ws + (kb & 1) * WB);
#pragma unroll
        for (int ks = 0; ks < 4; ++ks) {
            const int kl = ks * 8;
            const int ar = w * 16 + g;
            uint32_t a0 = Xu[ar * XS + kl + t];
            uint32_t a1 = Xu[(ar + 8) * XS + kl + t];
            uint32_t a2 = Xu[ar * XS + kl + t + 4];
            uint32_t a3 = Xu[(ar + 8) * XS + kl + t + 4];
            uint4 blo[4], bhi[4];
#pragma unroll
            for (int q = 0; q < 4; ++q) {
                blo[q] = *(const uint4*)&Wu[(kl + t) * WS + g * 16 + q * 4];
                bhi[q] = *(const uint4*)&Wu[(kl + t + 4) * WS + g * 16 + q * 4];
            }
#pragma unroll
            for (int nt = 0; nt < 16; ++nt) {
                uint32_t b0 = ((const uint32_t*)&blo[nt >> 2])[nt & 3];
                uint32_t b1 = ((const uint32_t*)&bhi[nt >> 2])[nt & 3];
                mma_tf32(c[nt], a0, a1, a2, a3, b0, b1);
            }
        }
        __syncthreads();
    }

    const int r1 = rowBase + w * 16 + g;
    const int r2 = r1 + 8;
    const bool v1 = r1 < N_NODES;
    const bool v2 = r2 < N_NODES;
#pragma unroll
    for (int nt = 0; nt < 16; ++nt) {
        int col = nt * 8 + 2 * t;
        if (v1) *(__half2*)&dstbuf[(size_t)r1 * 128 + col] =
            __float22half2_rn(make_float2(c[nt][0], c[nt][1]));
        if (v2) *(__half2*)&dstbuf[(size_t)r2 * 128 + col] =
            __float22half2_rn(make_float2(c[nt][2], c[nt][3]));
    }
}

// ---------------------------------------------------------------------------
// head (tf32 MMA): out[N,40] = h2[N,256] @ wfcr[256,40] + bfc
__global__ __launch_bounds__(256)
void head_tc(const float* __restrict__ bfc, float* __restrict__ out) {
    constexpr int XS = 36;
    constexpr int XB = 128 * XS;
    constexpr int WSTR = 44;

    extern __shared__ float smem[];
    float* Xs = smem;                  // 2 * XB floats
    float* Wsm = smem + 2 * XB;        // 256 * 44 floats

    const int tid = threadIdx.x;
    const int lane = tid & 31;
    const int w = tid >> 5;
    const int g = lane >> 2;
    const int t = lane & 3;
    const int rowBase = blockIdx.x * 128;

    const uint32_t xs_base = (uint32_t)__cvta_generic_to_shared(Xs);

    auto stageX = [&](int buf, int kb) {
#pragma unroll
        for (int it = 0; it < 4; ++it) {
            int idx = tid + it * 256;
            int r = idx >> 3, cc = idx & 7;
            int grow = min(rowBase + r, N_NODES - 1);
            uint32_t d = xs_base + (uint32_t)buf * XB * 4 + r * 144 + cc * 16;
            cp_cg(d, &g_h2[(size_t)grow * 256 + kb * 32 + cc * 4]);
        }
    };

    stageX(0, 0);
    cp_commit();

    for (int i = tid; i < 256 * 40; i += 256) {
        int k = i / 40, n = i % 40;
        Wsm[k * WSTR + n] = g_wfcr[i];
    }

    float c[5][4];
#pragma unroll
    for (int i = 0; i < 5; ++i) { c[i][0] = c[i][1] = c[i][2] = c[i][3] = 0.f; }

#pragma unroll
    for (int kb = 0; kb < 8; ++kb) {
        if (kb + 1 < 8) {
            stageX((kb + 1) & 1, kb + 1);
            cp_commit();
            cp_wait<1>();
        } else {
            cp_wait<0>();
        }
        __syncthreads();

        const uint32_t* Xu = (const uint32_t*)(Xs + (kb & 1) * XB);
#pragma unroll
        for (int ks = 0; ks < 4; ++ks) {
            const int kl = ks * 8;
            const int ar = w * 16 + g;
            uint32_t a0 = Xu[ar * XS + kl + t];
            uint32_t a1 = Xu[(ar + 8) * XS + kl + t];
            uint32_t a2 = Xu[ar * XS + kl + t + 4];
            uint32_t a3 = Xu[(ar + 8) * XS + kl + t + 4];
            const int krow = kb * 32 + kl;
#pragma unroll
            for (int nt = 0; nt < 5; ++nt) {
                uint32_t b0 = __float_as_uint(Wsm[(krow + t) * WSTR + nt * 8 + g]);
                uint32_t b1 = __float_as_uint(Wsm[(krow + t + 4) * WSTR + nt * 8 + g]);
                mma_tf32(c[nt], a0, a1, a2, a3, b0, b1);
            }
        }
        __syncthreads();
    }

    const int r1 = rowBase + w * 16 + g;
    const int r2 = r1 + 8;
#pragma unroll
    for (int nt = 0; nt < 5; ++nt) {
        int col = nt * 8 + 2 * t;
        float2 b = *(const float2*)&bfc[col];
        if (r1 < N_NODES) *(float2*)&out[(size_t)r1 * 40 + col] = make_float2(c[nt][0] + b.x, c[nt][1] + b.y);
        if (r2 < N_NODES) *(float2*)&out[(size_t)r2 * 40 + col] = make_float2(c[nt][2] + b.x, c[nt][3] + b.y);
    }
}

// ---------------------------------------------------------------------------
extern "C" void kernel_launch(void* const* d_in, const int* in_sizes, int n_in,
                              void* d_out, int out_size) {
    const float* x   = (const float*)d_in[0];
    const int*   src = (const int*)d_in[1];
    const int*   dst = (const int*)d_in[2];
    const float* w1s = (const float*)d_in[3];
    const float* b1s = (const float*)d_in[4];
    const float* w1n = (const float*)d_in[5];
    const float* b1n = (const float*)d_in[6];
    const float* w2s = (const float*)d_in[7];
    const float* b2s = (const float*)d_in[8];
    const float* w2n = (const float*)d_in[9];
    const float* b2n = (const float*)d_in[10];
    const float* wfc = (const float*)d_in[11];
    const float* bfc = (const float*)d_in[12];
    float* out = (float*)d_out;

    const int SMEM_GEMM = 2 * (128 * 36 + 32 * 132) * 4;         // 70656
    const int SMEM_HEAD = (2 * 128 * 36 + 256 * 44) * 4;         // 81920
    static int attr_done = 0;
    if (!attr_done) {
        cudaFuncSetAttribute(sage_gemm_tc<128>, cudaFuncAttributeMaxDynamicSharedMemorySize, SMEM_GEMM);
        cudaFuncSetAttribute(sage_gemm_tc<256>, cudaFuncAttributeMaxDynamicSharedMemorySize, SMEM_GEMM);
        cudaFuncSetAttribute(head_tc, cudaFuncAttributeMaxDynamicSharedMemorySize, SMEM_HEAD);
        attr_done = 1;
    }

    const dim3 gemm_grid((N_NODES + 127) / 128, 2);
    const int gath_blocks = (N_NODES + 7) / 8;
    const int edge_blocks = (N_EDGES + 255) / 256;
    const int head_blocks = (N_NODES + 127) / 128;

    // order keeps sage_gemm_tc<128> in the ncu capture slot (launch #4)
    zero_dc_kernel<<<(N_NODES + 255) / 256, 256>>>();                      // 1
    count_kernel<<<(N_EDGES / 4 + 255) / 256, 256>>>(dst);                 // 2
    prep_kernel<<<2048, 256>>>(x, w1n, w1s, w2n, w2s, wfc);                // 3
    sage_gemm_tc<128><<<gemm_grid, 256, SMEM_GEMM>>>(W1N_OFF, W1S_OFF);    // 4  <- profiled
    scan_kernel<<<1, 1024>>>();                                            // 5
    fill_kernel<<<edge_blocks, 256>>>(src, dst);                           // 6
    gather_epi_kernel<1><<<gath_blocks, 256>>>(b1s, b1n);                  // 7
    sage_gemm_tc<256><<<gemm_grid, 256, SMEM_GEMM>>>(W2N_OFF, W2S_OFF);    // 8
    gather_epi_kernel<2><<<gath_blocks, 256>>>(b2s, b2n);                  // 9
    head_tc<<<head_blocks, 256, SMEM_HEAD>>>(bfc, out);                    // 10
}